// round 8
// baseline (speedup 1.0000x reference)
#include <cuda_runtime.h>
#include <cuda_fp16.h>
#include <stdint.h>

// Fixed problem shapes
#define NLAT_IN   181
#define NLON_IN   360
#define NLAT_OUT  361
#define NLON_OUT  720
#define KSIZE     3
#define CIN       16
#define COUT      16
#define NNZ_MAX   8192

#define X_CI_STRIDE (NLAT_IN * NLON_IN)          // 65160
#define PLANE       (KSIZE * NLAT_IN * NLON_IN)  // 195480
#define NBINS       (NLAT_OUT * 2)               // 722 (lat, parity)
#define SCAN_P      768
#define SE_MAX      128

#define EIN_UNITS   (NLAT_IN * KSIZE)            // 543 einsum blocks (tin, k)
#define K1_BLOCKS   (EIN_UNITS + 1)              // +1 count/scan block

// Scratch (device globals — no dynamic allocation allowed)
__device__ uint4 g_xw8[2][PLANE];        // fp16-packed xw: plane cg = channels 8cg..8cg+7
__device__ int   g_starts[NBINS + 2];
__device__ int   g_cursor[NBINS];
__device__ int2  g_entries[NNZ_MAX];     // .x = base(18b)|shift<<18 ; .y = half2(v,v)

__constant__ float c_weight[COUT * CIN * KSIZE]; // 768 floats

// ---------------------------------------------------------------------------
// K1: einsum (blocks 0..542: one per (tin, k)) + count/scan (block 543).
__global__ __launch_bounds__(384) void einsum_binscan_kernel(
    const float* __restrict__ x, const int* __restrict__ col_idx, int nnz)
{
    const int b  = blockIdx.x;
    const int t  = threadIdx.x;
    const int nt = blockDim.x;   // 384

    if (b == EIN_UNITS) {
        // ---- count + scan only (fill is a separate parallel kernel) ----
        __shared__ int bufA[SCAN_P], bufB[SCAN_P];
        __shared__ int scnt[NBINS];

        for (int i = t; i < SCAN_P; i += nt) bufA[i] = 0;
        __syncthreads();
        for (int i = t; i < nnz; i += nt) {
            int col = col_idx[i];
            int hi  = col / NLON_OUT;
            atomicAdd(&bufA[hi * 2 + (col & 1)], 1);   // p parity == col parity
        }
        __syncthreads();
        for (int i = t; i < NBINS; i += nt) scnt[i] = bufA[i];
        __syncthreads();
        int* src = bufA; int* dst = bufB;
        for (int off = 1; off < SCAN_P; off <<= 1) {
            for (int i = t; i < SCAN_P; i += nt) {
                int v = src[i];
                if (i >= off) v += src[i - off];
                dst[i] = v;
            }
            __syncthreads();
            int* tmp = src; src = dst; dst = tmp;
        }
        for (int i = t; i < NBINS; i += nt) {
            g_starts[i + 1] = src[i];
            g_cursor[i]     = src[i] - scnt[i];   // exclusive prefix = bin start
        }
        if (t == 0) g_starts[0] = 0;
        return;
    }

    // ---- einsum block: (tin, k); 16 fp32 accumulators; weights in constant ----
    const int tin = b / KSIZE;
    const int k   = b - tin * KSIZE;
    if (t >= NLON_IN) return;

    const float* xb = x + tin * NLON_IN + t;

    float acc[16];
    #pragma unroll
    for (int c = 0; c < 16; c++) acc[c] = 0.0f;

    #pragma unroll
    for (int ci = 0; ci < CIN; ci++) {
        float xv = __ldg(xb + ci * X_CI_STRIDE);
        #pragma unroll
        for (int co = 0; co < 16; co++) {
            acc[co] = fmaf(c_weight[(co * CIN + ci) * KSIZE + k], xv, acc[co]);
        }
    }

    const int pos = (k * NLAT_IN + tin) * NLON_IN + t;
    {
        __half2 h01 = __floats2half2_rn(acc[0], acc[1]);
        __half2 h23 = __floats2half2_rn(acc[2], acc[3]);
        __half2 h45 = __floats2half2_rn(acc[4], acc[5]);
        __half2 h67 = __floats2half2_rn(acc[6], acc[7]);
        uint4 u;
        u.x = *reinterpret_cast<unsigned int*>(&h01);
        u.y = *reinterpret_cast<unsigned int*>(&h23);
        u.z = *reinterpret_cast<unsigned int*>(&h45);
        u.w = *reinterpret_cast<unsigned int*>(&h67);
        g_xw8[0][pos] = u;
    }
    {
        __half2 h01 = __floats2half2_rn(acc[8],  acc[9]);
        __half2 h23 = __floats2half2_rn(acc[10], acc[11]);
        __half2 h45 = __floats2half2_rn(acc[12], acc[13]);
        __half2 h67 = __floats2half2_rn(acc[14], acc[15]);
        uint4 u;
        u.x = *reinterpret_cast<unsigned int*>(&h01);
        u.y = *reinterpret_cast<unsigned int*>(&h23);
        u.z = *reinterpret_cast<unsigned int*>(&h45);
        u.w = *reinterpret_cast<unsigned int*>(&h67);
        g_xw8[1][pos] = u;
    }
}

// ---------------------------------------------------------------------------
// K2: parallel fill via global per-bin cursors.
__global__ void fill_kernel(const int* __restrict__ ker_idx,
                            const int* __restrict__ row_idx,
                            const int* __restrict__ col_idx,
                            const float* __restrict__ vals, int nnz)
{
    int i = blockIdx.x * blockDim.x + threadIdx.x;
    if (i >= nnz) return;
    int col = col_idx[i];
    int hi  = col / NLON_OUT;
    int p   = col - hi * NLON_OUT;
    int key = hi * 2 + (p & 1);
    int pos = atomicAdd(&g_cursor[key], 1);
    int base = (ker_idx[i] * NLAT_IN + row_idx[i]) * NLON_IN;  // < 2^18
    __half2 vh = __float2half2_rn(vals[i]);
    g_entries[pos] = make_int2(base | ((p >> 1) << 18),
                               (int)*reinterpret_cast<unsigned int*>(&vh));
}

// ---------------------------------------------------------------------------
// Entry decode: addr into plane + half2 value
__device__ __forceinline__ int dec_addr(int2 e, int t, __half2& vh) {
    unsigned ex = (unsigned)e.x;
    int shift = ex >> 18;
    int base  = ex & 0x3FFFF;
    float vbits; *(int*)&vbits = e.y;
    vh = *reinterpret_cast<__half2*>(&vbits);
    int idx = t - shift; if (idx < 0) idx += NLON_IN;
    return base + idx;
}

// Process one 4-entry batch from smem into 8 fp32 accumulators.
__device__ __forceinline__ void batch4(const int2* __restrict__ sePtr, int i, int t,
                                       const uint4* __restrict__ plane, float* acc)
{
    const __half2 hz = __float2half2_rn(0.0f);
    __half2 v0, v1, v2, v3;
    int a0 = dec_addr(sePtr[i + 0], t, v0);
    int a1 = dec_addr(sePtr[i + 1], t, v1);
    int a2 = dec_addr(sePtr[i + 2], t, v2);
    int a3 = dec_addr(sePtr[i + 3], t, v3);
    uint4 u0 = plane[a0];
    uint4 u1 = plane[a1];
    uint4 u2 = plane[a2];
    uint4 u3 = plane[a3];
    __half2 h0 = hz, h1 = hz, h2 = hz, h3 = hz;
    h0 = __hfma2(v0, *reinterpret_cast<__half2*>(&u0.x), h0);
    h1 = __hfma2(v0, *reinterpret_cast<__half2*>(&u0.y), h1);
    h2 = __hfma2(v0, *reinterpret_cast<__half2*>(&u0.z), h2);
    h3 = __hfma2(v0, *reinterpret_cast<__half2*>(&u0.w), h3);
    h0 = __hfma2(v1, *reinterpret_cast<__half2*>(&u1.x), h0);
    h1 = __hfma2(v1, *reinterpret_cast<__half2*>(&u1.y), h1);
    h2 = __hfma2(v1, *reinterpret_cast<__half2*>(&u1.z), h2);
    h3 = __hfma2(v1, *reinterpret_cast<__half2*>(&u1.w), h3);
    h0 = __hfma2(v2, *reinterpret_cast<__half2*>(&u2.x), h0);
    h1 = __hfma2(v2, *reinterpret_cast<__half2*>(&u2.y), h1);
    h2 = __hfma2(v2, *reinterpret_cast<__half2*>(&u2.z), h2);
    h3 = __hfma2(v2, *reinterpret_cast<__half2*>(&u2.w), h3);
    h0 = __hfma2(v3, *reinterpret_cast<__half2*>(&u3.x), h0);
    h1 = __hfma2(v3, *reinterpret_cast<__half2*>(&u3.y), h1);
    h2 = __hfma2(v3, *reinterpret_cast<__half2*>(&u3.z), h2);
    h3 = __hfma2(v3, *reinterpret_cast<__half2*>(&u3.w), h3);
    float2 f;
    f = __half22float2(h0); acc[0] += f.x; acc[1] += f.y;
    f = __half22float2(h1); acc[2] += f.x; acc[3] += f.y;
    f = __half22float2(h2); acc[4] += f.x; acc[5] += f.y;
    f = __half22float2(h3); acc[6] += f.x; acc[7] += f.y;
}

// K3: gather — grid (NLAT_OUT, 2). Block (ho, cg): thread t owns output lons
// (2t, 2t+1) for channels {8cg..8cg+7}. Entries staged in smem, each parity
// segment zero-padded to a multiple of 4 so the hot loop is branch-light.
__global__ __launch_bounds__(384) void gather_kernel(
    float* __restrict__ out, const float* __restrict__ bias)
{
    const int ho = blockIdx.x;
    const int cg = blockIdx.y;
    const int t  = threadIdx.x;
    const int nt = blockDim.x;

    __shared__ int2 se[SE_MAX + 8];
    __shared__ int shdr[3];
    if (t < 3) shdr[t] = g_starts[2 * ho + t];
    __syncthreads();
    const int s0 = shdr[0], s1 = shdr[1], s2 = shdr[2];
    const int nE = s1 - s0;
    const int nO = s2 - s1;
    const int nE4 = (nE + 3) & ~3;
    const int nO4 = (nO + 3) & ~3;

    const int2 zeroe = make_int2(0, 0);
    const bool fits = (nE4 + nO4) <= (SE_MAX + 8);
    if (fits) {
        for (int i = t; i < nE4; i += nt)
            se[i] = (i < nE) ? g_entries[s0 + i] : zeroe;
        for (int i = t; i < nO4; i += nt)
            se[nE4 + i] = (i < nO) ? g_entries[s1 + i] : zeroe;
    }
    __syncthreads();

    if (t >= NLON_IN) return;

    const uint4* __restrict__ plane = g_xw8[cg];

    float aE[8], aO[8];
    #pragma unroll
    for (int c = 0; c < 8; c++) { aE[c] = 0.0f; aO[c] = 0.0f; }

    if (fits) {
        for (int i = 0; i < nE4; i += 4) batch4(se, i, t, plane, aE);
        for (int i = 0; i < nO4; i += 4) batch4(se + nE4, i, t, plane, aO);
    } else {
        // fallback (statistically never for nnz=8192 over 722 bins)
        for (int i = s0; i < s1; i++) {
            __half2 v; int a = dec_addr(g_entries[i], t, v);
            uint4 u = plane[a];
            float vf = __half22float2(v).x;
            float2 g;
            g = __half22float2(*reinterpret_cast<__half2*>(&u.x));
            aE[0] = fmaf(vf, g.x, aE[0]); aE[1] = fmaf(vf, g.y, aE[1]);
            g = __half22float2(*reinterpret_cast<__half2*>(&u.y));
            aE[2] = fmaf(vf, g.x, aE[2]); aE[3] = fmaf(vf, g.y, aE[3]);
            g = __half22float2(*reinterpret_cast<__half2*>(&u.z));
            aE[4] = fmaf(vf, g.x, aE[4]); aE[5] = fmaf(vf, g.y, aE[5]);
            g = __half22float2(*reinterpret_cast<__half2*>(&u.w));
            aE[6] = fmaf(vf, g.x, aE[6]); aE[7] = fmaf(vf, g.y, aE[7]);
        }
        for (int i = s1; i < s2; i++) {
            __half2 v; int a = dec_addr(g_entries[i], t, v);
            uint4 u = plane[a];
            float vf = __half22float2(v).x;
            float2 g;
            g = __half22float2(*reinterpret_cast<__half2*>(&u.x));
            aO[0] = fmaf(vf, g.x, aO[0]); aO[1] = fmaf(vf, g.y, aO[1]);
            g = __half22float2(*reinterpret_cast<__half2*>(&u.y));
            aO[2] = fmaf(vf, g.x, aO[2]); aO[3] = fmaf(vf, g.y, aO[3]);
            g = __half22float2(*reinterpret_cast<__half2*>(&u.z));
            aO[4] = fmaf(vf, g.x, aO[4]); aO[5] = fmaf(vf, g.y, aO[5]);
            g = __half22float2(*reinterpret_cast<__half2*>(&u.w));
            aO[6] = fmaf(vf, g.x, aO[6]); aO[7] = fmaf(vf, g.y, aO[7]);
        }
    }

    #pragma unroll
    for (int c = 0; c < 8; c++) {
        int co = cg * 8 + c;
        float bb = __ldg(&bias[co]);
        float2* row = (float2*)(out + (size_t)co * (NLAT_OUT * NLON_OUT) + ho * NLON_OUT);
        row[t] = make_float2(aE[c] + bb, aO[c] + bb);
    }
}

// ---------------------------------------------------------------------------
extern "C" void kernel_launch(void* const* d_in, const int* in_sizes, int n_in,
                              void* d_out, int out_size) {
    const float* x       = (const float*)d_in[0];
    const float* weight  = (const float*)d_in[1];
    const float* bias    = (const float*)d_in[2];
    const int*   ker_idx = (const int*)d_in[3];
    const int*   row_idx = (const int*)d_in[4];
    const int*   col_idx = (const int*)d_in[5];
    const float* vals    = (const float*)d_in[6];
    float* out = (float*)d_out;

    int nnz = in_sizes[3];
    if (nnz > NNZ_MAX) nnz = NNZ_MAX;

    cudaMemcpyToSymbolAsync(c_weight, weight, COUT * CIN * KSIZE * sizeof(float),
                            0, cudaMemcpyDeviceToDevice, 0);

    einsum_binscan_kernel<<<K1_BLOCKS, 384>>>(x, col_idx, nnz);
    fill_kernel<<<(nnz + 255) / 256, 256>>>(ker_idx, row_idx, col_idx, vals, nnz);

    dim3 ggrid(NLAT_OUT, 2);
    gather_kernel<<<ggrid, 384>>>(out, bias);
}

// round 9
// speedup vs baseline: 1.1870x; 1.1870x over previous
#include <cuda_runtime.h>
#include <cuda_fp16.h>
#include <stdint.h>

// Fixed problem shapes
#define NLAT_IN   181
#define NLON_IN   360
#define NLAT_OUT  361
#define NLON_OUT  720
#define KSIZE     3
#define CIN       16
#define COUT      16
#define NNZ_MAX   8192

#define NPTS        (NLAT_IN * NLON_IN)          // 65160 points (tin,po)
#define NPT4        (NPTS / 4)                   // 16290 point-groups
#define PLANE       (KSIZE * NPTS)               // 195480
#define NBINS       (NLAT_OUT * 2)               // 722 (lat, parity) segments
#define SCAN_P      768
#define ENT_MAX     12288                        // 8192 + padding headroom

#define EIN_BLOCKS  384                          // 6 variants x 64 chunks
#define SCAN_BLOCK  EIN_BLOCKS                   // block 384
#define FILL_BLOCKS 32
#define K1_BLOCKS   (EIN_BLOCKS + 1 + FILL_BLOCKS)  // 417

// Scratch (device globals — zero-initialized at load; no dynamic allocation)
__device__ uint4 g_xw8[2][PLANE];       // fp16-packed xw: plane cg = channels 8cg..8cg+7
__device__ int   g_starts[NBINS + 2];
__device__ int   g_cursor[NBINS];
__device__ int2  g_entries[ENT_MAX];    // .x = base(18b)|shift<<18 ; .y = half2(v,v)
                                        // pad slots stay all-zero forever (v=0)
__device__ unsigned g_fillflag = 0;
__device__ unsigned g_filldone = 0;

// ---------------------------------------------------------------------------
// K1: einsum (blocks 0..383) + count/scan (block 384) + fill (blocks 385..416).
// All 417 blocks (256 thr, <=4 blocks/SM) are co-resident in one wave, so the
// fill blocks' spin-wait on the scan block's flag cannot deadlock.
__global__ __launch_bounds__(256, 4) void k1_kernel(
    const float* __restrict__ x, const float* __restrict__ weight,
    const int* __restrict__ ker_idx, const int* __restrict__ row_idx,
    const int* __restrict__ col_idx, const float* __restrict__ vals, int nnz)
{
    const int b  = blockIdx.x;
    const int t  = threadIdx.x;
    const int nt = blockDim.x;   // 256

    if (b < EIN_BLOCKS) {
        // ---- einsum: variant v = (k, cg half); 4 points per thread ----
        const int v     = b >> 6;        // 0..5
        const int chunk = b & 63;
        const int k     = v >> 1;        // 0..2
        const int cg    = v & 1;         // channel half

        __shared__ float4 sw4[32];       // [ (cc>=4)*16 + ci ] -> 4 weights
        if (t < 128) {
            int cc = t >> 4, ci = t & 15;
            ((float*)sw4)[((cc >> 2) * 16 + ci) * 4 + (cc & 3)] =
                weight[((cg * 8 + cc) * CIN + ci) * KSIZE + k];
        }
        __syncthreads();

        const int g = chunk * 256 + t;   // point-group id
        if (g >= NPT4) return;

        const float4* __restrict__ x4 = (const float4*)x;

        float4 acc[8];
        #pragma unroll
        for (int c = 0; c < 8; c++) acc[c] = make_float4(0.f, 0.f, 0.f, 0.f);

        #pragma unroll
        for (int ci = 0; ci < CIN; ci++) {
            float4 xv  = __ldg(&x4[ci * NPT4 + g]);
            float4 wlo = sw4[ci];
            float4 whi = sw4[16 + ci];
            acc[0].x = fmaf(wlo.x, xv.x, acc[0].x); acc[0].y = fmaf(wlo.x, xv.y, acc[0].y);
            acc[0].z = fmaf(wlo.x, xv.z, acc[0].z); acc[0].w = fmaf(wlo.x, xv.w, acc[0].w);
            acc[1].x = fmaf(wlo.y, xv.x, acc[1].x); acc[1].y = fmaf(wlo.y, xv.y, acc[1].y);
            acc[1].z = fmaf(wlo.y, xv.z, acc[1].z); acc[1].w = fmaf(wlo.y, xv.w, acc[1].w);
            acc[2].x = fmaf(wlo.z, xv.x, acc[2].x); acc[2].y = fmaf(wlo.z, xv.y, acc[2].y);
            acc[2].z = fmaf(wlo.z, xv.z, acc[2].z); acc[2].w = fmaf(wlo.z, xv.w, acc[2].w);
            acc[3].x = fmaf(wlo.w, xv.x, acc[3].x); acc[3].y = fmaf(wlo.w, xv.y, acc[3].y);
            acc[3].z = fmaf(wlo.w, xv.z, acc[3].z); acc[3].w = fmaf(wlo.w, xv.w, acc[3].w);
            acc[4].x = fmaf(whi.x, xv.x, acc[4].x); acc[4].y = fmaf(whi.x, xv.y, acc[4].y);
            acc[4].z = fmaf(whi.x, xv.z, acc[4].z); acc[4].w = fmaf(whi.x, xv.w, acc[4].w);
            acc[5].x = fmaf(whi.y, xv.x, acc[5].x); acc[5].y = fmaf(whi.y, xv.y, acc[5].y);
            acc[5].z = fmaf(whi.y, xv.z, acc[5].z); acc[5].w = fmaf(whi.y, xv.w, acc[5].w);
            acc[6].x = fmaf(whi.z, xv.x, acc[6].x); acc[6].y = fmaf(whi.z, xv.y, acc[6].y);
            acc[6].z = fmaf(whi.z, xv.z, acc[6].z); acc[6].w = fmaf(whi.z, xv.w, acc[6].w);
            acc[7].x = fmaf(whi.w, xv.x, acc[7].x); acc[7].y = fmaf(whi.w, xv.y, acc[7].y);
            acc[7].z = fmaf(whi.w, xv.z, acc[7].z); acc[7].w = fmaf(whi.w, xv.w, acc[7].w);
        }

        const int i0 = g * 4;
        uint4* __restrict__ dst = &g_xw8[cg][k * NPTS + i0];
        {
            __half2 h01 = __floats2half2_rn(acc[0].x, acc[1].x);
            __half2 h23 = __floats2half2_rn(acc[2].x, acc[3].x);
            __half2 h45 = __floats2half2_rn(acc[4].x, acc[5].x);
            __half2 h67 = __floats2half2_rn(acc[6].x, acc[7].x);
            dst[0] = make_uint4(*(unsigned*)&h01, *(unsigned*)&h23,
                                *(unsigned*)&h45, *(unsigned*)&h67);
        }
        {
            __half2 h01 = __floats2half2_rn(acc[0].y, acc[1].y);
            __half2 h23 = __floats2half2_rn(acc[2].y, acc[3].y);
            __half2 h45 = __floats2half2_rn(acc[4].y, acc[5].y);
            __half2 h67 = __floats2half2_rn(acc[6].y, acc[7].y);
            dst[1] = make_uint4(*(unsigned*)&h01, *(unsigned*)&h23,
                                *(unsigned*)&h45, *(unsigned*)&h67);
        }
        {
            __half2 h01 = __floats2half2_rn(acc[0].z, acc[1].z);
            __half2 h23 = __floats2half2_rn(acc[2].z, acc[3].z);
            __half2 h45 = __floats2half2_rn(acc[4].z, acc[5].z);
            __half2 h67 = __floats2half2_rn(acc[6].z, acc[7].z);
            dst[2] = make_uint4(*(unsigned*)&h01, *(unsigned*)&h23,
                                *(unsigned*)&h45, *(unsigned*)&h67);
        }
        {
            __half2 h01 = __floats2half2_rn(acc[0].w, acc[1].w);
            __half2 h23 = __floats2half2_rn(acc[2].w, acc[3].w);
            __half2 h45 = __floats2half2_rn(acc[4].w, acc[5].w);
            __half2 h67 = __floats2half2_rn(acc[6].w, acc[7].w);
            dst[3] = make_uint4(*(unsigned*)&h01, *(unsigned*)&h23,
                                *(unsigned*)&h45, *(unsigned*)&h67);
        }
        return;
    }

    if (b == SCAN_BLOCK) {
        // ---- count -> pad to x4 -> scan -> publish cursors + flag ----
        __shared__ int bufA[SCAN_P], bufB[SCAN_P];
        __shared__ int scnt[NBINS];

        for (int i = t; i < SCAN_P; i += nt) bufA[i] = 0;
        __syncthreads();
        for (int i = t; i < nnz; i += nt) {
            int col = col_idx[i];
            int hi  = col / NLON_OUT;
            atomicAdd(&bufA[hi * 2 + (col & 1)], 1);   // p parity == col parity
        }
        __syncthreads();
        for (int i = t; i < NBINS; i += nt) {
            int c4 = (bufA[i] + 3) & ~3;               // pad each segment to x4
            bufA[i] = c4;
            scnt[i] = c4;
        }
        __syncthreads();
        int* src = bufA; int* dst = bufB;
        for (int off = 1; off < SCAN_P; off <<= 1) {
            for (int i = t; i < SCAN_P; i += nt) {
                int vv = src[i];
                if (i >= off) vv += src[i - off];
                dst[i] = vv;
            }
            __syncthreads();
            int* tmp = src; src = dst; dst = tmp;
        }
        for (int i = t; i < NBINS; i += nt) {
            g_starts[i + 1] = src[i];
            g_cursor[i]     = src[i] - scnt[i];        // padded segment start
        }
        if (t == 0) g_starts[0] = 0;
        __threadfence();
        __syncthreads();
        if (t == 0) atomicExch(&g_fillflag, 1u);
        return;
    }

    // ---- fill blocks: spin until cursors published, then scatter entries ----
    {
        if (t == 0) {
            while (atomicAdd(&g_fillflag, 0u) == 0u) __nanosleep(64);
        }
        __syncthreads();
        __threadfence();

        int i = (b - SCAN_BLOCK - 1) * nt + t;
        if (i < nnz) {
            int col = col_idx[i];
            int hi  = col / NLON_OUT;
            int p   = col - hi * NLON_OUT;
            int key = hi * 2 + (p & 1);
            int pos = atomicAdd(&g_cursor[key], 1);
            int base = (ker_idx[i] * NLAT_IN + row_idx[i]) * NLON_IN;  // < 2^18
            __half2 vh = __float2half2_rn(vals[i]);
            g_entries[pos] = make_int2(base | ((p >> 1) << 18),
                                       (int)*(unsigned*)&vh);
        }
        __threadfence();
        __syncthreads();
        if (t == 0) {
            unsigned d = atomicAdd(&g_filldone, 1u);
            if (d == FILL_BLOCKS - 1) {            // last fill block resets state
                g_filldone = 0u;
                __threadfence();
                atomicExch(&g_fillflag, 0u);
            }
        }
    }
}

// ---------------------------------------------------------------------------
__device__ __forceinline__ int dec_addr(int2 e, int t, __half2& vh) {
    unsigned ex = (unsigned)e.x;
    int shift = ex >> 18;
    int base  = ex & 0x3FFFF;
    float vbits; *(int*)&vbits = e.y;
    vh = *reinterpret_cast<__half2*>(&vbits);
    int idx = t - shift; if (idx < 0) idx += NLON_IN;
    return base + idx;
}

__device__ __forceinline__ void batch4(const int2* __restrict__ ep, int i, int t,
                                       const uint4* __restrict__ plane, float* acc)
{
    const __half2 hz = __float2half2_rn(0.0f);
    int2 e0 = __ldg(&ep[i + 0]);
    int2 e1 = __ldg(&ep[i + 1]);
    int2 e2 = __ldg(&ep[i + 2]);
    int2 e3 = __ldg(&ep[i + 3]);
    __half2 v0, v1, v2, v3;
    int a0 = dec_addr(e0, t, v0);
    int a1 = dec_addr(e1, t, v1);
    int a2 = dec_addr(e2, t, v2);
    int a3 = dec_addr(e3, t, v3);
    uint4 u0 = __ldg(&plane[a0]);
    uint4 u1 = __ldg(&plane[a1]);
    uint4 u2 = __ldg(&plane[a2]);
    uint4 u3 = __ldg(&plane[a3]);
    __half2 h0 = hz, h1 = hz, h2 = hz, h3 = hz;
    h0 = __hfma2(v0, *(__half2*)&u0.x, h0);  h1 = __hfma2(v0, *(__half2*)&u0.y, h1);
    h2 = __hfma2(v0, *(__half2*)&u0.z, h2);  h3 = __hfma2(v0, *(__half2*)&u0.w, h3);
    h0 = __hfma2(v1, *(__half2*)&u1.x, h0);  h1 = __hfma2(v1, *(__half2*)&u1.y, h1);
    h2 = __hfma2(v1, *(__half2*)&u1.z, h2);  h3 = __hfma2(v1, *(__half2*)&u1.w, h3);
    h0 = __hfma2(v2, *(__half2*)&u2.x, h0);  h1 = __hfma2(v2, *(__half2*)&u2.y, h1);
    h2 = __hfma2(v2, *(__half2*)&u2.z, h2);  h3 = __hfma2(v2, *(__half2*)&u2.w, h3);
    h0 = __hfma2(v3, *(__half2*)&u3.x, h0);  h1 = __hfma2(v3, *(__half2*)&u3.y, h1);
    h2 = __hfma2(v3, *(__half2*)&u3.z, h2);  h3 = __hfma2(v3, *(__half2*)&u3.w, h3);
    float2 f;
    f = __half22float2(h0); acc[0] += f.x; acc[1] += f.y;
    f = __half22float2(h1); acc[2] += f.x; acc[3] += f.y;
    f = __half22float2(h2); acc[4] += f.x; acc[5] += f.y;
    f = __half22float2(h3); acc[6] += f.x; acc[7] += f.y;
}

// K2: gather — grid (NLAT_OUT, 2). Thread t owns output lons (2t, 2t+1) for
// channels {8cg..8cg+7}. Segments are pre-padded to x4 with zero entries:
// no staging, no syncs, no tails, no branches in the hot loop.
__global__ __launch_bounds__(384) void gather_kernel(
    float* __restrict__ out, const float* __restrict__ bias)
{
    const int ho = blockIdx.x;
    const int cg = blockIdx.y;
    const int t  = threadIdx.x;
    if (t >= NLON_IN) return;

    const int s0 = __ldg(&g_starts[2 * ho]);
    const int s1 = __ldg(&g_starts[2 * ho + 1]);
    const int s2 = __ldg(&g_starts[2 * ho + 2]);

    const uint4* __restrict__ plane = g_xw8[cg];

    float aE[8], aO[8];
    #pragma unroll
    for (int c = 0; c < 8; c++) { aE[c] = 0.0f; aO[c] = 0.0f; }

    for (int i = s0; i < s1; i += 4) batch4(g_entries, i, t, plane, aE);
    for (int i = s1; i < s2; i += 4) batch4(g_entries, i, t, plane, aO);

    #pragma unroll
    for (int c = 0; c < 8; c++) {
        int co = cg * 8 + c;
        float bb = __ldg(&bias[co]);
        float2* row = (float2*)(out + (size_t)co * (NLAT_OUT * NLON_OUT) + ho * NLON_OUT);
        row[t] = make_float2(aE[c] + bb, aO[c] + bb);
    }
}

// ---------------------------------------------------------------------------
extern "C" void kernel_launch(void* const* d_in, const int* in_sizes, int n_in,
                              void* d_out, int out_size) {
    const float* x       = (const float*)d_in[0];
    const float* weight  = (const float*)d_in[1];
    const float* bias    = (const float*)d_in[2];
    const int*   ker_idx = (const int*)d_in[3];
    const int*   row_idx = (const int*)d_in[4];
    const int*   col_idx = (const int*)d_in[5];
    const float* vals    = (const float*)d_in[6];
    float* out = (float*)d_out;

    int nnz = in_sizes[3];
    if (nnz > NNZ_MAX) nnz = NNZ_MAX;

    k1_kernel<<<K1_BLOCKS, 256>>>(x, weight, ker_idx, row_idx, col_idx, vals, nnz);

    dim3 ggrid(NLAT_OUT, 2);
    gather_kernel<<<ggrid, 384>>>(out, bias);
}

// round 10
// speedup vs baseline: 1.2821x; 1.0801x over previous
#include <cuda_runtime.h>
#include <cuda_fp16.h>
#include <stdint.h>

// Fixed problem shapes
#define NLAT_IN   181
#define NLON_IN   360
#define NLAT_OUT  361
#define NLON_OUT  720
#define KSIZE     3
#define CIN       16
#define COUT      16
#define NNZ_MAX   8192

#define NPTS        (NLAT_IN * NLON_IN)          // 65160
#define NPT2        (NPTS / 2)                   // 32580 point-pairs
#define PLANE       (KSIZE * NPTS)               // 195480
#define NBINS       (NLAT_OUT * 2)               // 722 (lat, parity) segments
#define SCAN_P      768
#define ENT_MAX     12288

#define NBLOCKS     592                          // 148 SMs x 4 blocks, co-resident
#define EIN_CHUNKS  85                           // ceil(NPT2 / 384)
#define EIN_UNITS   (6 * EIN_CHUNKS)             // 510 (k x cg x chunk)
#define CNT_BLOCKS  22                           // 22 x 384 >= 8192
#define CNT_BASE    EIN_UNITS                    // 510..531
#define SCAN_BID    (EIN_UNITS + CNT_BLOCKS)     // 532
#define MASTER_TGT  (EIN_UNITS + CNT_BLOCKS)     // einsum done + scatter done
#define GUNITS      (NLAT_OUT * 2)               // 722 gather units (ho, cg)

// Scratch (device globals — zero-initialized at load; no dynamic allocation)
__device__ uint4 g_xw8[2][PLANE];       // fp16-packed xw: plane cg = channels 8cg..8cg+7
__device__ int   g_count[NBINS];
__device__ int   g_starts[NBINS + 2];
__device__ int   g_cursor[NBINS];
__device__ int2  g_entries[ENT_MAX];    // pad slots stay all-zero forever (v=0)
__device__ unsigned g_cntA = 0;         // count blocks finished
__device__ unsigned g_scanflag = 0;     // scanner published cursors
__device__ unsigned g_master = 0;       // einsum blocks + scatter blocks finished
__device__ unsigned g_work = 0;         // gather work-stealing counter
__device__ unsigned g_exit = 0;         // exit counter (last block resets state)

__device__ __forceinline__ unsigned vld(unsigned* p) {
    return *((volatile unsigned*)p);
}

__device__ __forceinline__ int dec_addr(int2 e, int t, __half2& vh) {
    unsigned ex = (unsigned)e.x;
    int shift = ex >> 18;
    int base  = ex & 0x3FFFF;
    float vbits; *(int*)&vbits = e.y;
    vh = *reinterpret_cast<__half2*>(&vbits);
    int idx = t - shift; if (idx < 0) idx += NLON_IN;
    return base + idx;
}

__device__ __forceinline__ void batch4(const int2* __restrict__ ep, int i, int t,
                                       const uint4* __restrict__ plane, float* acc)
{
    const __half2 hz = __float2half2_rn(0.0f);
    int2 e0 = __ldg(&ep[i + 0]);
    int2 e1 = __ldg(&ep[i + 1]);
    int2 e2 = __ldg(&ep[i + 2]);
    int2 e3 = __ldg(&ep[i + 3]);
    __half2 v0, v1, v2, v3;
    int a0 = dec_addr(e0, t, v0);
    int a1 = dec_addr(e1, t, v1);
    int a2 = dec_addr(e2, t, v2);
    int a3 = dec_addr(e3, t, v3);
    uint4 u0 = __ldg(&plane[a0]);
    uint4 u1 = __ldg(&plane[a1]);
    uint4 u2 = __ldg(&plane[a2]);
    uint4 u3 = __ldg(&plane[a3]);
    __half2 h0 = hz, h1 = hz, h2 = hz, h3 = hz;
    h0 = __hfma2(v0, *(__half2*)&u0.x, h0);  h1 = __hfma2(v0, *(__half2*)&u0.y, h1);
    h2 = __hfma2(v0, *(__half2*)&u0.z, h2);  h3 = __hfma2(v0, *(__half2*)&u0.w, h3);
    h0 = __hfma2(v1, *(__half2*)&u1.x, h0);  h1 = __hfma2(v1, *(__half2*)&u1.y, h1);
    h2 = __hfma2(v1, *(__half2*)&u1.z, h2);  h3 = __hfma2(v1, *(__half2*)&u1.w, h3);
    h0 = __hfma2(v2, *(__half2*)&u2.x, h0);  h1 = __hfma2(v2, *(__half2*)&u2.y, h1);
    h2 = __hfma2(v2, *(__half2*)&u2.z, h2);  h3 = __hfma2(v2, *(__half2*)&u2.w, h3);
    h0 = __hfma2(v3, *(__half2*)&u3.x, h0);  h1 = __hfma2(v3, *(__half2*)&u3.y, h1);
    h2 = __hfma2(v3, *(__half2*)&u3.z, h2);  h3 = __hfma2(v3, *(__half2*)&u3.w, h3);
    float2 f;
    f = __half22float2(h0); acc[0] += f.x; acc[1] += f.y;
    f = __half22float2(h1); acc[2] += f.x; acc[3] += f.y;
    f = __half22float2(h2); acc[4] += f.x; acc[5] += f.y;
    f = __half22float2(h3); acc[6] += f.x; acc[7] += f.y;
}

// ---------------------------------------------------------------------------
// One persistent kernel: 592 blocks, all co-resident (4/SM forced).
// Phase A roles by bid: [0,510) einsum, [510,532) count+scatter, 532 scan.
// Spin barrier on g_master, then all blocks work-steal gather units.
__global__ __launch_bounds__(384, 4) void fused_kernel(
    const float* __restrict__ x, const float* __restrict__ weight,
    const int* __restrict__ ker_idx, const int* __restrict__ row_idx,
    const int* __restrict__ col_idx, const float* __restrict__ vals,
    const float* __restrict__ bias, float* __restrict__ out, int nnz)
{
    const int b  = blockIdx.x;
    const int t  = threadIdx.x;
    const int nt = blockDim.x;   // 384

    __shared__ int s_arena[2 * SCAN_P + NBINS];   // scanner only (~9 KB)
    __shared__ int s_u;

    // ======================= PHASE A =======================
    if (b < EIN_UNITS) {
        // ---- einsum: (k, cg); thread = 2 points, 8 channels ----
        const int v     = b / EIN_CHUNKS;
        const int chunk = b - v * EIN_CHUNKS;
        const int k     = v >> 1;
        const int cg    = v & 1;

        __shared__ float sw[128];
        if (t < 128) {
            int cc = t >> 4, ci = t & 15;
            sw[((cc >> 2) * 16 + ci) * 4 + (cc & 3)] =
                weight[((cg * 8 + cc) * CIN + ci) * KSIZE + k];
        }
        __syncthreads();

        const int g = chunk * 384 + t;
        if (g < NPT2) {
            const float2* __restrict__ x2 = (const float2*)x;
            const float4* __restrict__ w4 = (const float4*)sw;

            float2 acc[8];
            #pragma unroll
            for (int c = 0; c < 8; c++) acc[c] = make_float2(0.f, 0.f);

            #pragma unroll
            for (int ci = 0; ci < CIN; ci++) {
                float2 xv  = __ldg(&x2[ci * NPT2 + g]);
                float4 wlo = w4[ci];
                float4 whi = w4[16 + ci];
                acc[0].x = fmaf(wlo.x, xv.x, acc[0].x); acc[0].y = fmaf(wlo.x, xv.y, acc[0].y);
                acc[1].x = fmaf(wlo.y, xv.x, acc[1].x); acc[1].y = fmaf(wlo.y, xv.y, acc[1].y);
                acc[2].x = fmaf(wlo.z, xv.x, acc[2].x); acc[2].y = fmaf(wlo.z, xv.y, acc[2].y);
                acc[3].x = fmaf(wlo.w, xv.x, acc[3].x); acc[3].y = fmaf(wlo.w, xv.y, acc[3].y);
                acc[4].x = fmaf(whi.x, xv.x, acc[4].x); acc[4].y = fmaf(whi.x, xv.y, acc[4].y);
                acc[5].x = fmaf(whi.y, xv.x, acc[5].x); acc[5].y = fmaf(whi.y, xv.y, acc[5].y);
                acc[6].x = fmaf(whi.z, xv.x, acc[6].x); acc[6].y = fmaf(whi.z, xv.y, acc[6].y);
                acc[7].x = fmaf(whi.w, xv.x, acc[7].x); acc[7].y = fmaf(whi.w, xv.y, acc[7].y);
            }

            uint4* __restrict__ dst = &g_xw8[cg][k * NPTS + g * 2];
            {
                __half2 h01 = __floats2half2_rn(acc[0].x, acc[1].x);
                __half2 h23 = __floats2half2_rn(acc[2].x, acc[3].x);
                __half2 h45 = __floats2half2_rn(acc[4].x, acc[5].x);
                __half2 h67 = __floats2half2_rn(acc[6].x, acc[7].x);
                dst[0] = make_uint4(*(unsigned*)&h01, *(unsigned*)&h23,
                                    *(unsigned*)&h45, *(unsigned*)&h67);
            }
            {
                __half2 h01 = __floats2half2_rn(acc[0].y, acc[1].y);
                __half2 h23 = __floats2half2_rn(acc[2].y, acc[3].y);
                __half2 h45 = __floats2half2_rn(acc[4].y, acc[5].y);
                __half2 h67 = __floats2half2_rn(acc[6].y, acc[7].y);
                dst[1] = make_uint4(*(unsigned*)&h01, *(unsigned*)&h23,
                                    *(unsigned*)&h45, *(unsigned*)&h67);
            }
        }
        __threadfence();
        __syncthreads();
        if (t == 0) atomicAdd(&g_master, 1u);
    }
    else if (b < SCAN_BID) {
        // ---- count block: histogram my slice into global bins ----
        const int slice = b - CNT_BASE;
        const int i = slice * nt + t;
        int col = 0, hi = 0, p = 0;
        bool valid = (i < nnz);
        if (valid) {
            col = col_idx[i];
            hi  = col / NLON_OUT;
            p   = col - hi * NLON_OUT;
            atomicAdd(&g_count[hi * 2 + (p & 1)], 1);
        }
        __threadfence();
        __syncthreads();
        if (t == 0) atomicAdd(&g_cntA, 1u);

        // wait for scanner to publish cursors
        if (t == 0) { while (vld(&g_scanflag) == 0u) __nanosleep(128); }
        __syncthreads();
        __threadfence();

        // zero my stripe of g_count for the next graph replay (scanner is done with it)
        if (t < 33) {
            int bin = slice * 33 + t;
            if (bin < NBINS) g_count[bin] = 0;
        }

        // scatter my slice
        if (valid) {
            int key = hi * 2 + (p & 1);
            int pos = atomicAdd(&g_cursor[key], 1);
            int base = (ker_idx[i] * NLAT_IN + row_idx[i]) * NLON_IN;  // < 2^18
            __half2 vh = __float2half2_rn(vals[i]);
            g_entries[pos] = make_int2(base | ((p >> 1) << 18), (int)*(unsigned*)&vh);
        }
        __threadfence();
        __syncthreads();
        if (t == 0) atomicAdd(&g_master, 1u);
    }
    else if (b == SCAN_BID) {
        // ---- scanner: wait counts, pad to x4, scan, publish ----
        if (t == 0) { while (vld(&g_cntA) < CNT_BLOCKS) __nanosleep(128); }
        __syncthreads();
        __threadfence();

        int* bufA = s_arena;
        int* bufB = s_arena + SCAN_P;
        int* scnt = s_arena + 2 * SCAN_P;

        for (int i = t; i < SCAN_P; i += nt) {
            int c = (i < NBINS) ? g_count[i] : 0;
            int c4 = (c + 3) & ~3;             // pad each segment to x4
            bufA[i] = c4;
            if (i < NBINS) scnt[i] = c4;
        }
        __syncthreads();
        int* src = bufA; int* dst = bufB;
        for (int off = 1; off < SCAN_P; off <<= 1) {
            for (int i = t; i < SCAN_P; i += nt) {
                int vv = src[i];
                if (i >= off) vv += src[i - off];
                dst[i] = vv;
            }
            __syncthreads();
            int* tmp = src; src = dst; dst = tmp;
        }
        for (int i = t; i < NBINS; i += nt) {
            g_starts[i + 1] = src[i];
            g_cursor[i]     = src[i] - scnt[i];   // padded segment start
        }
        if (t == 0) g_starts[0] = 0;
        __threadfence();
        __syncthreads();
        if (t == 0) atomicExch(&g_scanflag, 1u);
    }
    // blocks >= 533 fall straight through to the barrier

    // ======================= BARRIER: wait for xw + entries =======================
    if (t == 0) { while (vld(&g_master) < MASTER_TGT) __nanosleep(128); }
    __syncthreads();
    __threadfence();

    // ======================= PHASE B: work-stealing gather =======================
    while (true) {
        __syncthreads();
        if (t == 0) s_u = (int)atomicAdd(&g_work, 1u);
        __syncthreads();
        const int u = s_u;
        if (u >= GUNITS) break;

        const int ho = u >> 1;
        const int cg = u & 1;
        if (t >= NLON_IN) continue;

        const int s0 = __ldg(&g_starts[2 * ho]);
        const int s1 = __ldg(&g_starts[2 * ho + 1]);
        const int s2 = __ldg(&g_starts[2 * ho + 2]);

        const uint4* __restrict__ plane = g_xw8[cg];

        float aE[8], aO[8];
        #pragma unroll
        for (int c = 0; c < 8; c++) { aE[c] = 0.0f; aO[c] = 0.0f; }

        for (int i = s0; i < s1; i += 4) batch4(g_entries, i, t, plane, aE);
        for (int i = s1; i < s2; i += 4) batch4(g_entries, i, t, plane, aO);

        #pragma unroll
        for (int c = 0; c < 8; c++) {
            int co = cg * 8 + c;
            float bb = __ldg(&bias[co]);
            float2* row = (float2*)(out + (size_t)co * (NLAT_OUT * NLON_OUT)
                                    + ho * NLON_OUT);
            row[t] = make_float2(aE[c] + bb, aO[c] + bb);
        }
    }

    // ======================= EXIT: last block resets state =======================
    __syncthreads();
    if (t == 0) {
        unsigned e = atomicAdd(&g_exit, 1u);
        if (e == NBLOCKS - 1) {
            g_master = 0u;
            g_cntA = 0u;
            g_scanflag = 0u;
            g_work = 0u;
            __threadfence();
            g_exit = 0u;
        }
    }
}

// ---------------------------------------------------------------------------
extern "C" void kernel_launch(void* const* d_in, const int* in_sizes, int n_in,
                              void* d_out, int out_size) {
    const float* x       = (const float*)d_in[0];
    const float* weight  = (const float*)d_in[1];
    const float* bias    = (const float*)d_in[2];
    const int*   ker_idx = (const int*)d_in[3];
    const int*   row_idx = (const int*)d_in[4];
    const int*   col_idx = (const int*)d_in[5];
    const float* vals    = (const float*)d_in[6];
    float* out = (float*)d_out;

    int nnz = in_sizes[3];
    if (nnz > NNZ_MAX) nnz = NNZ_MAX;

    fused_kernel<<<NBLOCKS, 384>>>(x, weight, ker_idx, row_idx, col_idx, vals,
                                   bias, out, nnz);
}

// round 11
// speedup vs baseline: 1.3774x; 1.0743x over previous
#include <cuda_runtime.h>
#include <cuda_fp16.h>
#include <stdint.h>

// Fixed problem shapes
#define NLAT_IN   181
#define NLON_IN   360
#define NLAT_OUT  361
#define NLON_OUT  720
#define KSIZE     3
#define CIN       16
#define COUT      16
#define NNZ_MAX   8192

#define NPTS        (NLAT_IN * NLON_IN)          // 65160
#define NPT4        (NPTS / 4)                   // 16290 point-quads
#define PLANE       (KSIZE * NPTS)               // 195480
#define NBINS       (NLAT_OUT * 2)               // 722 (lat, parity) segments
#define SCAN_P      768
#define ENT_MAX     12288
#define SE_CAP      160                          // per-row staged entries cap

#define NBLOCKS     444                          // 148 SMs x 3 blocks, co-resident
#define EIN_CHUNKS  43                           // ceil(NPT4 / 384)
#define EIN_UNITS   (6 * EIN_CHUNKS)             // 258 (k x cg x chunk)
#define CNT_BLOCKS  22                           // 22 x 384 >= 8192
#define CNT_BASE    EIN_UNITS                    // 258..279
#define SCAN_BID    (EIN_UNITS + CNT_BLOCKS)     // 280
#define MASTER_TGT  (EIN_UNITS + CNT_BLOCKS)     // einsum + scatter done
#define GUNITS      (NLAT_OUT * 2)               // 722 gather units (ho, cg)

// Scratch (device globals — zero-initialized at load; no dynamic allocation)
__device__ uint4 g_xw8[2][PLANE];       // fp16-packed xw: plane cg = channels 8cg..8cg+7
__device__ int   g_count[NBINS];
__device__ int   g_starts[NBINS + 2];
__device__ int   g_cursor[NBINS];
__device__ int2  g_entries[ENT_MAX];    // pad slots stay all-zero forever (v=0)
__device__ unsigned g_cntA = 0;
__device__ unsigned g_scanflag = 0;
__device__ unsigned g_master = 0;
__device__ unsigned g_work = 0;
__device__ unsigned g_exit = 0;

__device__ __forceinline__ unsigned vld(unsigned* p) {
    return *((volatile unsigned*)p);
}

__device__ __forceinline__ int dec_addr(int2 e, int t, __half2& vh) {
    unsigned ex = (unsigned)e.x;
    int shift = ex >> 18;
    int base  = ex & 0x3FFFF;
    float vbits; *(int*)&vbits = e.y;
    vh = *reinterpret_cast<__half2*>(&vbits);
    int idx = t - shift; if (idx < 0) idx += NLON_IN;
    return base + idx;
}

// 4-entry batch; entries come from SMEM (address-space inferred after inlining).
__device__ __forceinline__ void batch4_s(const int2* ep, int i, int t,
                                         const uint4* __restrict__ plane, float* acc)
{
    const __half2 hz = __float2half2_rn(0.0f);
    int2 e0 = ep[i + 0];
    int2 e1 = ep[i + 1];
    int2 e2 = ep[i + 2];
    int2 e3 = ep[i + 3];
    __half2 v0, v1, v2, v3;
    int a0 = dec_addr(e0, t, v0);
    int a1 = dec_addr(e1, t, v1);
    int a2 = dec_addr(e2, t, v2);
    int a3 = dec_addr(e3, t, v3);
    uint4 u0 = __ldg(&plane[a0]);
    uint4 u1 = __ldg(&plane[a1]);
    uint4 u2 = __ldg(&plane[a2]);
    uint4 u3 = __ldg(&plane[a3]);
    __half2 h0 = hz, h1 = hz, h2 = hz, h3 = hz;
    h0 = __hfma2(v0, *(__half2*)&u0.x, h0);  h1 = __hfma2(v0, *(__half2*)&u0.y, h1);
    h2 = __hfma2(v0, *(__half2*)&u0.z, h2);  h3 = __hfma2(v0, *(__half2*)&u0.w, h3);
    h0 = __hfma2(v1, *(__half2*)&u1.x, h0);  h1 = __hfma2(v1, *(__half2*)&u1.y, h1);
    h2 = __hfma2(v1, *(__half2*)&u1.z, h2);  h3 = __hfma2(v1, *(__half2*)&u1.w, h3);
    h0 = __hfma2(v2, *(__half2*)&u2.x, h0);  h1 = __hfma2(v2, *(__half2*)&u2.y, h1);
    h2 = __hfma2(v2, *(__half2*)&u2.z, h2);  h3 = __hfma2(v2, *(__half2*)&u2.w, h3);
    h0 = __hfma2(v3, *(__half2*)&u3.x, h0);  h1 = __hfma2(v3, *(__half2*)&u3.y, h1);
    h2 = __hfma2(v3, *(__half2*)&u3.z, h2);  h3 = __hfma2(v3, *(__half2*)&u3.w, h3);
    float2 f;
    f = __half22float2(h0); acc[0] += f.x; acc[1] += f.y;
    f = __half22float2(h1); acc[2] += f.x; acc[3] += f.y;
    f = __half22float2(h2); acc[4] += f.x; acc[5] += f.y;
    f = __half22float2(h3); acc[6] += f.x; acc[7] += f.y;
}

// Global-memory variant (fallback path only).
__device__ __forceinline__ void batch4_g(const int2* __restrict__ ep, int i, int t,
                                         const uint4* __restrict__ plane, float* acc)
{
    const __half2 hz = __float2half2_rn(0.0f);
    int2 e0 = __ldg(&ep[i + 0]);
    int2 e1 = __ldg(&ep[i + 1]);
    int2 e2 = __ldg(&ep[i + 2]);
    int2 e3 = __ldg(&ep[i + 3]);
    __half2 v0, v1, v2, v3;
    int a0 = dec_addr(e0, t, v0);
    int a1 = dec_addr(e1, t, v1);
    int a2 = dec_addr(e2, t, v2);
    int a3 = dec_addr(e3, t, v3);
    uint4 u0 = __ldg(&plane[a0]);
    uint4 u1 = __ldg(&plane[a1]);
    uint4 u2 = __ldg(&plane[a2]);
    uint4 u3 = __ldg(&plane[a3]);
    __half2 h0 = hz, h1 = hz, h2 = hz, h3 = hz;
    h0 = __hfma2(v0, *(__half2*)&u0.x, h0);  h1 = __hfma2(v0, *(__half2*)&u0.y, h1);
    h2 = __hfma2(v0, *(__half2*)&u0.z, h2);  h3 = __hfma2(v0, *(__half2*)&u0.w, h3);
    h0 = __hfma2(v1, *(__half2*)&u1.x, h0);  h1 = __hfma2(v1, *(__half2*)&u1.y, h1);
    h2 = __hfma2(v1, *(__half2*)&u1.z, h2);  h3 = __hfma2(v1, *(__half2*)&u1.w, h3);
    h0 = __hfma2(v2, *(__half2*)&u2.x, h0);  h1 = __hfma2(v2, *(__half2*)&u2.y, h1);
    h2 = __hfma2(v2, *(__half2*)&u2.z, h2);  h3 = __hfma2(v2, *(__half2*)&u2.w, h3);
    h0 = __hfma2(v3, *(__half2*)&u3.x, h0);  h1 = __hfma2(v3, *(__half2*)&u3.y, h1);
    h2 = __hfma2(v3, *(__half2*)&u3.z, h2);  h3 = __hfma2(v3, *(__half2*)&u3.w, h3);
    float2 f;
    f = __half22float2(h0); acc[0] += f.x; acc[1] += f.y;
    f = __half22float2(h1); acc[2] += f.x; acc[3] += f.y;
    f = __half22float2(h2); acc[4] += f.x; acc[5] += f.y;
    f = __half22float2(h3); acc[6] += f.x; acc[7] += f.y;
}

// ---------------------------------------------------------------------------
// One persistent kernel: 444 blocks, all co-resident (3/SM forced).
// Phase A roles by bid: [0,258) einsum, [258,280) count+scatter, 280 scan,
// [281,444) idle->barrier. Then all blocks work-steal gather units.
__global__ __launch_bounds__(384, 3) void fused_kernel(
    const float* __restrict__ x, const float* __restrict__ weight,
    const int* __restrict__ ker_idx, const int* __restrict__ row_idx,
    const int* __restrict__ col_idx, const float* __restrict__ vals,
    const float* __restrict__ bias, float* __restrict__ out, int nnz)
{
    const int b  = blockIdx.x;
    const int t  = threadIdx.x;
    const int nt = blockDim.x;   // 384

    __shared__ int s_arena[2 * SCAN_P + NBINS];   // scanner / staging arena
    __shared__ int s_u;

    // ======================= PHASE A =======================
    if (b < EIN_UNITS) {
        // ---- einsum: (k, cg); thread = 4 points, 8 channels ----
        const int v     = b / EIN_CHUNKS;
        const int chunk = b - v * EIN_CHUNKS;
        const int k     = v >> 1;
        const int cg    = v & 1;

        __shared__ float sw[128];
        if (t < 128) {
            int cc = t >> 4, ci = t & 15;
            sw[((cc >> 2) * 16 + ci) * 4 + (cc & 3)] =
                weight[((cg * 8 + cc) * CIN + ci) * KSIZE + k];
        }
        __syncthreads();

        const int g = chunk * 384 + t;
        if (g < NPT4) {
            const float4* __restrict__ x4 = (const float4*)x;
            const float4* __restrict__ w4 = (const float4*)sw;

            float4 acc[8];
            #pragma unroll
            for (int c = 0; c < 8; c++) acc[c] = make_float4(0.f, 0.f, 0.f, 0.f);

            #pragma unroll
            for (int ci = 0; ci < CIN; ci++) {
                float4 xv  = __ldg(&x4[ci * NPT4 + g]);
                float4 wlo = w4[ci];
                float4 whi = w4[16 + ci];
                acc[0].x = fmaf(wlo.x, xv.x, acc[0].x); acc[0].y = fmaf(wlo.x, xv.y, acc[0].y);
                acc[0].z = fmaf(wlo.x, xv.z, acc[0].z); acc[0].w = fmaf(wlo.x, xv.w, acc[0].w);
                acc[1].x = fmaf(wlo.y, xv.x, acc[1].x); acc[1].y = fmaf(wlo.y, xv.y, acc[1].y);
                acc[1].z = fmaf(wlo.y, xv.z, acc[1].z); acc[1].w = fmaf(wlo.y, xv.w, acc[1].w);
                acc[2].x = fmaf(wlo.z, xv.x, acc[2].x); acc[2].y = fmaf(wlo.z, xv.y, acc[2].y);
                acc[2].z = fmaf(wlo.z, xv.z, acc[2].z); acc[2].w = fmaf(wlo.z, xv.w, acc[2].w);
                acc[3].x = fmaf(wlo.w, xv.x, acc[3].x); acc[3].y = fmaf(wlo.w, xv.y, acc[3].y);
                acc[3].z = fmaf(wlo.w, xv.z, acc[3].z); acc[3].w = fmaf(wlo.w, xv.w, acc[3].w);
                acc[4].x = fmaf(whi.x, xv.x, acc[4].x); acc[4].y = fmaf(whi.x, xv.y, acc[4].y);
                acc[4].z = fmaf(whi.x, xv.z, acc[4].z); acc[4].w = fmaf(whi.x, xv.w, acc[4].w);
                acc[5].x = fmaf(whi.y, xv.x, acc[5].x); acc[5].y = fmaf(whi.y, xv.y, acc[5].y);
                acc[5].z = fmaf(whi.y, xv.z, acc[5].z); acc[5].w = fmaf(whi.y, xv.w, acc[5].w);
                acc[6].x = fmaf(whi.z, xv.x, acc[6].x); acc[6].y = fmaf(whi.z, xv.y, acc[6].y);
                acc[6].z = fmaf(whi.z, xv.z, acc[6].z); acc[6].w = fmaf(whi.z, xv.w, acc[6].w);
                acc[7].x = fmaf(whi.w, xv.x, acc[7].x); acc[7].y = fmaf(whi.w, xv.y, acc[7].y);
                acc[7].z = fmaf(whi.w, xv.z, acc[7].z); acc[7].w = fmaf(whi.w, xv.w, acc[7].w);
            }

            uint4* __restrict__ dst = &g_xw8[cg][k * NPTS + g * 4];
            {
                __half2 h01 = __floats2half2_rn(acc[0].x, acc[1].x);
                __half2 h23 = __floats2half2_rn(acc[2].x, acc[3].x);
                __half2 h45 = __floats2half2_rn(acc[4].x, acc[5].x);
                __half2 h67 = __floats2half2_rn(acc[6].x, acc[7].x);
                dst[0] = make_uint4(*(unsigned*)&h01, *(unsigned*)&h23,
                                    *(unsigned*)&h45, *(unsigned*)&h67);
            }
            {
                __half2 h01 = __floats2half2_rn(acc[0].y, acc[1].y);
                __half2 h23 = __floats2half2_rn(acc[2].y, acc[3].y);
                __half2 h45 = __floats2half2_rn(acc[4].y, acc[5].y);
                __half2 h67 = __floats2half2_rn(acc[6].y, acc[7].y);
                dst[1] = make_uint4(*(unsigned*)&h01, *(unsigned*)&h23,
                                    *(unsigned*)&h45, *(unsigned*)&h67);
            }
            {
                __half2 h01 = __floats2half2_rn(acc[0].z, acc[1].z);
                __half2 h23 = __floats2half2_rn(acc[2].z, acc[3].z);
                __half2 h45 = __floats2half2_rn(acc[4].z, acc[5].z);
                __half2 h67 = __floats2half2_rn(acc[6].z, acc[7].z);
                dst[2] = make_uint4(*(unsigned*)&h01, *(unsigned*)&h23,
                                    *(unsigned*)&h45, *(unsigned*)&h67);
            }
            {
                __half2 h01 = __floats2half2_rn(acc[0].w, acc[1].w);
                __half2 h23 = __floats2half2_rn(acc[2].w, acc[3].w);
                __half2 h45 = __floats2half2_rn(acc[4].w, acc[5].w);
                __half2 h67 = __floats2half2_rn(acc[6].w, acc[7].w);
                dst[3] = make_uint4(*(unsigned*)&h01, *(unsigned*)&h23,
                                    *(unsigned*)&h45, *(unsigned*)&h67);
            }
        }
        __threadfence();
        __syncthreads();
        if (t == 0) atomicAdd(&g_master, 1u);
    }
    else if (b < SCAN_BID) {
        // ---- count block: histogram my slice, then wait & scatter ----
        const int slice = b - CNT_BASE;
        const int i = slice * nt + t;
        int col = 0, hi = 0, p = 0;
        bool valid = (i < nnz);
        if (valid) {
            col = col_idx[i];
            hi  = col / NLON_OUT;
            p   = col - hi * NLON_OUT;
            atomicAdd(&g_count[hi * 2 + (p & 1)], 1);
        }
        __threadfence();
        __syncthreads();
        if (t == 0) atomicAdd(&g_cntA, 1u);

        if (t == 0) { while (vld(&g_scanflag) == 0u) __nanosleep(128); }
        __syncthreads();
        __threadfence();

        // zero my stripe of g_count for the next graph replay
        if (t < 33) {
            int bin = slice * 33 + t;
            if (bin < NBINS) g_count[bin] = 0;
        }

        if (valid) {
            int key = hi * 2 + (p & 1);
            int pos = atomicAdd(&g_cursor[key], 1);
            int base = (ker_idx[i] * NLAT_IN + row_idx[i]) * NLON_IN;  // < 2^18
            __half2 vh = __float2half2_rn(vals[i]);
            g_entries[pos] = make_int2(base | ((p >> 1) << 18), (int)*(unsigned*)&vh);
        }
        __threadfence();
        __syncthreads();
        if (t == 0) atomicAdd(&g_master, 1u);
    }
    else if (b == SCAN_BID) {
        // ---- scanner: wait counts, pad to x4, scan, publish ----
        if (t == 0) { while (vld(&g_cntA) < CNT_BLOCKS) __nanosleep(128); }
        __syncthreads();
        __threadfence();

        int* bufA = s_arena;
        int* bufB = s_arena + SCAN_P;
        int* scnt = s_arena + 2 * SCAN_P;

        for (int i = t; i < SCAN_P; i += nt) {
            int c = (i < NBINS) ? g_count[i] : 0;
            int c4 = (c + 3) & ~3;
            bufA[i] = c4;
            if (i < NBINS) scnt[i] = c4;
        }
        __syncthreads();
        int* src = bufA; int* dst = bufB;
        for (int off = 1; off < SCAN_P; off <<= 1) {
            for (int i = t; i < SCAN_P; i += nt) {
                int vv = src[i];
                if (i >= off) vv += src[i - off];
                dst[i] = vv;
            }
            __syncthreads();
            int* tmp = src; src = dst; dst = tmp;
        }
        for (int i = t; i < NBINS; i += nt) {
            g_starts[i + 1] = src[i];
            g_cursor[i]     = src[i] - scnt[i];
        }
        if (t == 0) g_starts[0] = 0;
        __threadfence();
        __syncthreads();
        if (t == 0) atomicExch(&g_scanflag, 1u);
    }
    // blocks >= 281 fall straight through to the barrier

    // ======================= BARRIER =======================
    if (t == 0) { while (vld(&g_master) < MASTER_TGT) __nanosleep(128); }
    __syncthreads();
    __threadfence();

    // ======================= PHASE B: work-stealing gather =======================
    int2* se = (int2*)s_arena;                     // reuse arena for entry staging

    while (true) {
        __syncthreads();                           // protects se + s_u reuse
        if (t == 0) s_u = (int)atomicAdd(&g_work, 1u);
        __syncthreads();
        const int u = s_u;
        if (u >= GUNITS) break;

        const int ho = u >> 1;
        const int cg = u & 1;

        const int s0 = __ldg(&g_starts[2 * ho]);
        const int s1 = __ldg(&g_starts[2 * ho + 1]);
        const int s2 = __ldg(&g_starts[2 * ho + 2]);
        const int n4 = s2 - s0;
        const bool fits = (n4 <= SE_CAP);

        if (fits) {
            for (int i = t; i < n4; i += nt) se[i] = g_entries[s0 + i];
        }
        __syncthreads();

        if (t >= NLON_IN) continue;

        const uint4* __restrict__ plane = g_xw8[cg];
        const int nE4 = s1 - s0;
        const int nO4 = s2 - s1;

        float aE[8], aO[8];
        #pragma unroll
        for (int c = 0; c < 8; c++) { aE[c] = 0.0f; aO[c] = 0.0f; }

        if (fits) {
            // paired E/O chains -> 8 plane loads in flight
            int jE = 0, jO = 0;
            int jm = (nE4 > nO4) ? nE4 : nO4;
            for (int j = 0; j < jm; j += 4) {
                if (jE < nE4) { batch4_s(se, jE, t, plane, aE); jE += 4; }
                if (jO < nO4) { batch4_s(se + nE4, jO, t, plane, aO); jO += 4; }
            }
        } else {
            for (int i = 0; i < nE4; i += 4) batch4_g(&g_entries[s0], i, t, plane, aE);
            for (int i = 0; i < nO4; i += 4) batch4_g(&g_entries[s1], i, t, plane, aO);
        }

        #pragma unroll
        for (int c = 0; c < 8; c++) {
            int co = cg * 8 + c;
            float bb = __ldg(&bias[co]);
            float2* row = (float2*)(out + (size_t)co * (NLAT_OUT * NLON_OUT)
                                    + ho * NLON_OUT);
            row[t] = make_float2(aE[c] + bb, aO[c] + bb);
        }
    }

    // ======================= EXIT: last block resets state =======================
    __syncthreads();
    if (t == 0) {
        unsigned e = atomicAdd(&g_exit, 1u);
        if (e == NBLOCKS - 1) {
            g_master = 0u;
            g_cntA = 0u;
            g_scanflag = 0u;
            g_work = 0u;
            __threadfence();
            g_exit = 0u;
        }
    }
}

// ---------------------------------------------------------------------------
extern "C" void kernel_launch(void* const* d_in, const int* in_sizes, int n_in,
                              void* d_out, int out_size) {
    const float* x       = (const float*)d_in[0];
    const float* weight  = (const float*)d_in[1];
    const float* bias    = (const float*)d_in[2];
    const int*   ker_idx = (const int*)d_in[3];
    const int*   row_idx = (const int*)d_in[4];
    const int*   col_idx = (const int*)d_in[5];
    const float* vals    = (const float*)d_in[6];
    float* out = (float*)d_out;

    int nnz = in_sizes[3];
    if (nnz > NNZ_MAX) nnz = NNZ_MAX;

    fused_kernel<<<NBLOCKS, 384>>>(x, weight, ker_idx, row_idx, col_idx, vals,
                                   bias, out, nnz);
}